// round 4
// baseline (speedup 1.0000x reference)
#include <cuda_runtime.h>
#include <cstdint>

#define NSTATES 35
#define NB      64
#define TT      512
#define DDIM    2496
#define BTROWS  (NB * TT)   // 32768

// Scratch (no cudaMalloc allowed)
__device__ float g_w[(size_t)BTROWS * NSTATES];  // exp((m_sq - 2 x.m)/-500), ~4.6 MB
__device__ float g_xsqp[NB][16];                 // per-batch partial |x|^2 sums

// ---------------------------------------------------------------------------
// tf32 warp-MMA GEMM  w[bt][s] = exp((m_sq[s] - 2*x.m)/-500)
// MT=2 m-tiles (32 rows/warp), 5 n-tiles (40 cols), K=2496.
// m_sq computed in-warp from streamed B values (no prep kernel).
// |x|^2 partials written race-free to g_xsqp (summed in k_fwd).
// ---------------------------------------------------------------------------
#define MT  2
#define NTL 5

__device__ __forceinline__ void mma_tf32(float* d,
    uint32_t a0, uint32_t a1, uint32_t a2, uint32_t a3,
    uint32_t b0, uint32_t b1) {
    asm volatile(
        "mma.sync.aligned.m16n8k8.row.col.f32.tf32.tf32.f32 "
        "{%0,%1,%2,%3}, {%4,%5,%6,%7}, {%8,%9}, {%0,%1,%2,%3};\n"
        : "+f"(d[0]), "+f"(d[1]), "+f"(d[2]), "+f"(d[3])
        : "r"(a0), "r"(a1), "r"(a2), "r"(a3), "r"(b0), "r"(b1));
}

__global__ void __launch_bounds__(128) k_gemm(const float* __restrict__ x,
                                              const float* __restrict__ mM) {
    __shared__ float msq_s[4][40];
    const int wid  = threadIdx.x >> 5;
    const int warp = blockIdx.x * 4 + wid;
    const int lane = threadIdx.x & 31;
    const int g = lane >> 2;        // 0..7
    const int c = lane & 3;         // 0..3
    const int row0 = warp * (MT * 16);   // 32 rows per warp

    const float* pa[MT][2];
#pragma unroll
    for (int mt = 0; mt < MT; mt++) {
        pa[mt][0] = x + (size_t)(row0 + mt * 16 + g)     * DDIM + 2 * c;
        pa[mt][1] = x + (size_t)(row0 + mt * 16 + g + 8) * DDIM + 2 * c;
    }
    const float* pb[NTL];
    bool bvalid[NTL];
#pragma unroll
    for (int nt = 0; nt < NTL; nt++) {
        int s = nt * 8 + g;
        bvalid[nt] = (s < NSTATES);
        int sc = s < NSTATES ? s : (NSTATES - 1);
        pb[nt] = mM + (size_t)sc * DDIM + 2 * c;
    }

    float acc[MT][NTL][4];
#pragma unroll
    for (int mt = 0; mt < MT; mt++)
#pragma unroll
        for (int nt = 0; nt < NTL; nt++)
#pragma unroll
            for (int i = 0; i < 4; i++) acc[mt][nt][i] = 0.f;

    float xsq[MT][2];
#pragma unroll
    for (int mt = 0; mt < MT; mt++) { xsq[mt][0] = 0.f; xsq[mt][1] = 0.f; }
    float bsq[NTL];
#pragma unroll
    for (int nt = 0; nt < NTL; nt++) bsq[nt] = 0.f;

#pragma unroll 4
    for (int kk = 0; kk < DDIM; kk += 8) {
        float2 alo[MT], ahi[MT];
#pragma unroll
        for (int mt = 0; mt < MT; mt++) {
            alo[mt] = *(const float2*)(pa[mt][0] + kk);
            ahi[mt] = *(const float2*)(pa[mt][1] + kk);
        }
        float2 bv[NTL];
#pragma unroll
        for (int nt = 0; nt < NTL; nt++) {
            float2 t = *(const float2*)(pb[nt] + kk);
            bv[nt].x = bvalid[nt] ? t.x : 0.f;
            bv[nt].y = bvalid[nt] ? t.y : 0.f;
        }
#pragma unroll
        for (int nt = 0; nt < NTL; nt++) {
            bsq[nt] = fmaf(bv[nt].x, bv[nt].x, bsq[nt]);
            bsq[nt] = fmaf(bv[nt].y, bv[nt].y, bsq[nt]);
        }
#pragma unroll
        for (int mt = 0; mt < MT; mt++) {
            xsq[mt][0] = fmaf(alo[mt].x, alo[mt].x, xsq[mt][0]);
            xsq[mt][0] = fmaf(alo[mt].y, alo[mt].y, xsq[mt][0]);
            xsq[mt][1] = fmaf(ahi[mt].x, ahi[mt].x, xsq[mt][1]);
            xsq[mt][1] = fmaf(ahi[mt].y, ahi[mt].y, xsq[mt][1]);
#pragma unroll
            for (int nt = 0; nt < NTL; nt++) {
                mma_tf32(acc[mt][nt],
                         __float_as_uint(alo[mt].x), __float_as_uint(ahi[mt].x),
                         __float_as_uint(alo[mt].y), __float_as_uint(ahi[mt].y),
                         __float_as_uint(bv[nt].x),  __float_as_uint(bv[nt].y));
            }
        }
    }

    // m_sq[s] = sum over c-quad of bsq  (lane layout: lane = g*4+c)
#pragma unroll
    for (int nt = 0; nt < NTL; nt++) {
        float v = bsq[nt];
        v += __shfl_xor_sync(0xffffffffu, v, 1);
        v += __shfl_xor_sync(0xffffffffu, v, 2);
        if (c == 0) msq_s[wid][nt * 8 + g] = v;
    }
    __syncwarp();

    // Epilogue: w = exp((m_sq - 2*xm) * (-1/500)), stored row-major [bt][35]
    const float NEG_INV = -1.0f / 500.0f;
#pragma unroll
    for (int mt = 0; mt < MT; mt++) {
#pragma unroll
        for (int h = 0; h < 2; h++) {
            int row = row0 + mt * 16 + g + h * 8;
#pragma unroll
            for (int nt = 0; nt < NTL; nt++) {
                int col = nt * 8 + 2 * c;
                float v0 = acc[mt][nt][2 * h + 0];
                float v1 = acc[mt][nt][2 * h + 1];
                float w0 = __expf((msq_s[wid][col]     - 2.f * v0) * NEG_INV);
                float w1 = __expf((msq_s[wid][col + 1] - 2.f * v1) * NEG_INV);
                if (col < NSTATES)
                    g_w[(size_t)row * NSTATES + col] = w0;
                if (col + 1 < NSTATES)
                    g_w[(size_t)row * NSTATES + col + 1] = w1;
            }
        }
    }

    // |x|^2 partial: warp covers 32 rows, all inside batch b = row0>>9.
    float tot = 0.f;
#pragma unroll
    for (int mt = 0; mt < MT; mt++) tot += xsq[mt][0] + xsq[mt][1];
    tot += __shfl_xor_sync(0xffffffffu, tot, 16);
    tot += __shfl_xor_sync(0xffffffffu, tot, 8);
    tot += __shfl_xor_sync(0xffffffffu, tot, 4);
    tot += __shfl_xor_sync(0xffffffffu, tot, 2);
    tot += __shfl_xor_sync(0xffffffffu, tot, 1);
    if (lane == 0) g_xsqp[row0 >> 9][warp & 15] = tot;
}

// ---------------------------------------------------------------------------
// Forward recursion (linear domain), pipelined scalar-sum formulation.
// p'_j = w_j*(Λ[p]_j + eps*S);   S' = Σ_j (w_j Λ[p]_j) + eps*S*(Σ_j w_j)
// The Σr butterfly overlaps the next step's shift work; only a scalar FMA
// couples consecutive steps through S. Lanes 0..31: states 0..31 (p);
// lanes 0..2 additionally hold states 32..34 (q).
// ---------------------------------------------------------------------------
__device__ __forceinline__ float bfly_sum(float v) {
    const unsigned FULL = 0xffffffffu;
    v += __shfl_xor_sync(FULL, v, 16);
    v += __shfl_xor_sync(FULL, v, 8);
    v += __shfl_xor_sync(FULL, v, 4);
    v += __shfl_xor_sync(FULL, v, 2);
    v += __shfl_xor_sync(FULL, v, 1);
    return v;
}

struct FwdLane {
    int i1, i2, iF;
    bool is0, lt2, lt3;
};

__device__ __forceinline__ void fwd_step(float& p, float& q, float& S,
                                         float wp, float wq, const FwdLane& L) {
    const unsigned FULL = 0xffffffffu;
    const float EPS = 0.02f / 35.0f;
    // shift shuffles first (critical path)
    float A1 = __shfl_up_sync(FULL, p, 1);     // p[l-1]
    float A2 = __shfl_up_sync(FULL, p, 2);     // p[l-2]
    float Cr = __shfl_sync(FULL, q, L.i1);
    float Dr = __shfl_sync(FULL, q, L.i2);
    float Fv = __shfl_sync(FULL, p, L.iF);
    float Gv = __shfl_sync(FULL, p, 31);
    // W = sum of w over states (data-only; off critical path)
    float Wt = bfly_sum(wp + wq);              // wq == 0 on lanes >= 3
    float pm1 = L.is0 ? Cr : A1;
    float pm2 = L.lt2 ? Dr : A2;
    float qm1 = L.is0 ? Gv : Cr;
    float qm2 = L.lt2 ? Fv : Dr;
    float sp = fmaf(0.1f, p, fmaf(0.8f, pm1, 0.08f * pm2));
    float sq = fmaf(0.1f, q, fmaf(0.8f, qm1, 0.08f * qm2));
    float rp = wp * sp;
    float rq = L.lt3 ? (wq * sq) : 0.0f;
    float sigma = EPS * S;                     // S from previous step's scalar chain
    p = fmaf(sigma, wp, rp);
    q = L.lt3 ? fmaf(sigma, wq, rq) : 0.0f;
    float R = bfly_sum(rp + rq);               // latency overlapped with next step
    S = fmaf(sigma, Wt, R);                    // S = sum of the NEW p
}

__global__ void __launch_bounds__(32) k_fwd(float* __restrict__ out) {
    const int b = blockIdx.x;
    const int l = threadIdx.x;
    const float* wb = g_w + (size_t)b * TT * NSTATES;
    const float NEG_INV = -1.0f / 500.0f;

    // |x|^2 offset
    float part = (l < 16) ? g_xsqp[b][l] : 0.0f;
    float xoff = bfly_sum(part) * NEG_INV;

    FwdLane L;
    L.i1 = (l + 2) % 3;
    L.i2 = (l + 1) % 3;
    L.iF = (30 + l) & 31;
    L.is0 = (l == 0);
    L.lt2 = (l < 2);
    L.lt3 = (l < 3);

    // t = 0: alpha0 = emis0 + prior; prior = +10 (s=0), -10 else; shift by 10.
    const float EXPM20 = 2.0611536e-09f;
    float p = wb[l] * (L.is0 ? 1.0f : EXPM20);
    float q = L.lt3 ? (wb[32 + l] * EXPM20) : 0.0f;
    float Cacc = 10.0f;
    float S = bfly_sum(p + q);

    // prefetch ring (depth 4) for w — loads only, no dependent ops
    float bufp[4], bufq[4];
#pragma unroll
    for (int d = 0; d < 4; d++) {
        int t = 1 + d;
        bufp[d] = __ldg(wb + t * NSTATES + l);
        bufq[d] = L.lt3 ? __ldg(wb + t * NSTATES + 32 + l) : 0.0f;
    }

    int t = 1;
    for (int it = 0; it < 127; it++) {        // 127*4 = 508 steps: t = 1..508
#pragma unroll
        for (int u = 0; u < 4; u++) {
            fwd_step(p, q, S, bufp[u], bufq[u], L);
            int tn = t + 4;
            if (tn < TT) {
                bufp[u] = __ldg(wb + tn * NSTATES + l);
                bufq[u] = L.lt3 ? __ldg(wb + tn * NSTATES + 32 + l) : 0.0f;
            }
            if ((t & 15) == 0) {
                float rs = __fdividef(1.0f, S);
                Cacc += __logf(S);
                p *= rs;
                q *= rs;
                S *= rs;   // keep S consistent with scaled p
            }
            t++;
        }
    }
#pragma unroll
    for (int u = 0; u < 3; u++) {             // t = 509, 510, 511
        fwd_step(p, q, S, bufp[u], bufq[u], L);
        t++;
    }

    float v = bfly_sum(p + (L.lt3 ? q : 0.0f));
    if (l == 0) out[b] = __logf(v) + Cacc + xoff;
}

// ---------------------------------------------------------------------------
extern "C" void kernel_launch(void* const* d_in, const int* in_sizes, int n_in,
                              void* d_out, int out_size) {
    const float* obs = (const float*)d_in[0];  // [64,512,16,13,12]
    const float* m   = (const float*)d_in[1];  // [35,16,13,12]
    float* out = (float*)d_out;                // [64]

    k_gemm<<<BTROWS / 128, 128>>>(obs, m);     // 256 CTAs x 4 warps x 32 rows
    k_fwd<<<NB, 32>>>(out);
}

// round 5
// speedup vs baseline: 1.2234x; 1.2234x over previous
#include <cuda_runtime.h>
#include <cstdint>

#define NSTATES 35
#define NPAD    40
#define NB      64
#define TT      512
#define DDIM    2496
#define BTROWS  (NB * TT)   // 32768

// Scratch (no cudaMalloc allowed). +16 rows padding so k_fwd prefetch never branches.
__device__ float g_w[(size_t)(BTROWS + 16) * NPAD];  // exp((m_sq - 2 x.m)/-500), 40-padded
__device__ float g_wsum[BTROWS + 16];                // per-(b,t) sum of w over 35 states
__device__ float g_xsqp[NB][16];                     // per-batch partial |x|^2 sums

// ---------------------------------------------------------------------------
// bf16 warp-MMA GEMM  w[bt][s] = exp((m_sq[s] - 2*x.m)/-500)
// m16n8k16, MT=2 m-tiles (32 rows/warp), 5 n-tiles (40 cols incl. pad), K=2496.
// m_sq computed in-warp from streamed fp32 B values (exact).
// Row sums of w (Wt) computed in epilogue. |x|^2 partials exact fp32.
// ---------------------------------------------------------------------------
#define MT  2
#define NTL 5

__device__ __forceinline__ uint32_t cvt_bf2(float2 v) {
    uint32_t r;
    asm("cvt.rn.bf16x2.f32 %0, %1, %2;" : "=r"(r) : "f"(v.y), "f"(v.x));
    return r;   // low half = v.x (lower k), high = v.y
}

__device__ __forceinline__ void mma_bf16(float* d,
    uint32_t a0, uint32_t a1, uint32_t a2, uint32_t a3,
    uint32_t b0, uint32_t b1) {
    asm volatile(
        "mma.sync.aligned.m16n8k16.row.col.f32.bf16.bf16.f32 "
        "{%0,%1,%2,%3}, {%4,%5,%6,%7}, {%8,%9}, {%0,%1,%2,%3};\n"
        : "+f"(d[0]), "+f"(d[1]), "+f"(d[2]), "+f"(d[3])
        : "r"(a0), "r"(a1), "r"(a2), "r"(a3), "r"(b0), "r"(b1));
}

__global__ void __launch_bounds__(128) k_gemm(const float* __restrict__ x,
                                              const float* __restrict__ mM) {
    __shared__ float msq_s[4][40];
    const int wid  = threadIdx.x >> 5;
    const int warp = blockIdx.x * 4 + wid;
    const int lane = threadIdx.x & 31;
    const int g = lane >> 2;        // 0..7
    const int c = lane & 3;         // 0..3
    const int row0 = warp * (MT * 16);   // 32 rows per warp

    const float* pa[MT][2];
#pragma unroll
    for (int mt = 0; mt < MT; mt++) {
        pa[mt][0] = x + (size_t)(row0 + mt * 16 + g)     * DDIM + 2 * c;
        pa[mt][1] = x + (size_t)(row0 + mt * 16 + g + 8) * DDIM + 2 * c;
    }
    const float* pb[NTL];
    bool bvalid[NTL];
#pragma unroll
    for (int nt = 0; nt < NTL; nt++) {
        int s = nt * 8 + g;
        bvalid[nt] = (s < NSTATES);
        int sc = s < NSTATES ? s : (NSTATES - 1);
        pb[nt] = mM + (size_t)sc * DDIM + 2 * c;
    }

    float acc[MT][NTL][4];
#pragma unroll
    for (int mt = 0; mt < MT; mt++)
#pragma unroll
        for (int nt = 0; nt < NTL; nt++)
#pragma unroll
            for (int i = 0; i < 4; i++) acc[mt][nt][i] = 0.f;

    float xsq = 0.f;
    float bsq[NTL];
#pragma unroll
    for (int nt = 0; nt < NTL; nt++) bsq[nt] = 0.f;

#pragma unroll 2
    for (int kk = 0; kk < DDIM; kk += 16) {
        // A: MT tiles x rows {g, g+8} x k-halves {2c, 8+2c}
        float2 af[MT][2][2];
#pragma unroll
        for (int mt = 0; mt < MT; mt++) {
#pragma unroll
            for (int r = 0; r < 2; r++) {
                af[mt][r][0] = *(const float2*)(pa[mt][r] + kk);
                af[mt][r][1] = *(const float2*)(pa[mt][r] + kk + 8);
            }
        }
        // B: NTL tiles x k-halves
        float2 bf[NTL][2];
#pragma unroll
        for (int nt = 0; nt < NTL; nt++) {
            float2 t0 = *(const float2*)(pb[nt] + kk);
            float2 t1 = *(const float2*)(pb[nt] + kk + 8);
            bf[nt][0].x = bvalid[nt] ? t0.x : 0.f;
            bf[nt][0].y = bvalid[nt] ? t0.y : 0.f;
            bf[nt][1].x = bvalid[nt] ? t1.x : 0.f;
            bf[nt][1].y = bvalid[nt] ? t1.y : 0.f;
        }
        // exact fp32 squared sums
#pragma unroll
        for (int mt = 0; mt < MT; mt++)
#pragma unroll
            for (int r = 0; r < 2; r++)
#pragma unroll
                for (int h = 0; h < 2; h++) {
                    xsq = fmaf(af[mt][r][h].x, af[mt][r][h].x, xsq);
                    xsq = fmaf(af[mt][r][h].y, af[mt][r][h].y, xsq);
                }
#pragma unroll
        for (int nt = 0; nt < NTL; nt++)
#pragma unroll
            for (int h = 0; h < 2; h++) {
                bsq[nt] = fmaf(bf[nt][h].x, bf[nt][h].x, bsq[nt]);
                bsq[nt] = fmaf(bf[nt][h].y, bf[nt][h].y, bsq[nt]);
            }
        // convert + MMA
        uint32_t A[MT][4];
#pragma unroll
        for (int mt = 0; mt < MT; mt++) {
            A[mt][0] = cvt_bf2(af[mt][0][0]);
            A[mt][1] = cvt_bf2(af[mt][1][0]);
            A[mt][2] = cvt_bf2(af[mt][0][1]);
            A[mt][3] = cvt_bf2(af[mt][1][1]);
        }
#pragma unroll
        for (int nt = 0; nt < NTL; nt++) {
            uint32_t B0 = cvt_bf2(bf[nt][0]);
            uint32_t B1 = cvt_bf2(bf[nt][1]);
#pragma unroll
            for (int mt = 0; mt < MT; mt++)
                mma_bf16(acc[mt][nt], A[mt][0], A[mt][1], A[mt][2], A[mt][3], B0, B1);
        }
    }

    // m_sq[s] = sum over c-quad of bsq  (bsq covers col s = nt*8+g across k-quarters)
#pragma unroll
    for (int nt = 0; nt < NTL; nt++) {
        float v = bsq[nt];
        v += __shfl_xor_sync(0xffffffffu, v, 1);
        v += __shfl_xor_sync(0xffffffffu, v, 2);
        if (c == 0) msq_s[wid][nt * 8 + g] = v;
    }
    __syncwarp();

    // Epilogue: w = exp((m_sq - 2*xm) * (-1/500)), stored [bt][40] (pad cols = 0),
    // plus per-row Wt sums.
    const float NEG_INV = -1.0f / 500.0f;
#pragma unroll
    for (int mt = 0; mt < MT; mt++) {
#pragma unroll
        for (int h = 0; h < 2; h++) {
            int row = row0 + mt * 16 + g + h * 8;
            float rowsum = 0.f;
#pragma unroll
            for (int nt = 0; nt < NTL; nt++) {
                int col = nt * 8 + 2 * c;
                float v0 = acc[mt][nt][2 * h + 0];
                float v1 = acc[mt][nt][2 * h + 1];
                float w0 = __expf((msq_s[wid][col]     - 2.f * v0) * NEG_INV);
                float w1 = __expf((msq_s[wid][col + 1] - 2.f * v1) * NEG_INV);
                w0 = (col     < NSTATES) ? w0 : 0.f;
                w1 = (col + 1 < NSTATES) ? w1 : 0.f;
                rowsum += w0 + w1;
                float2 wv = make_float2(w0, w1);
                *(float2*)(&g_w[(size_t)row * NPAD + col]) = wv;
            }
            // row sum over all 40 cols (pads are 0): reduce over c-quad
            rowsum += __shfl_xor_sync(0xffffffffu, rowsum, 1);
            rowsum += __shfl_xor_sync(0xffffffffu, rowsum, 2);
            if (c == 0) g_wsum[row] = rowsum;
        }
    }

    // |x|^2 partial: warp covers 32 rows, all inside batch b = row0>>9.
    float tot = xsq;
    tot += __shfl_xor_sync(0xffffffffu, tot, 16);
    tot += __shfl_xor_sync(0xffffffffu, tot, 8);
    tot += __shfl_xor_sync(0xffffffffu, tot, 4);
    tot += __shfl_xor_sync(0xffffffffu, tot, 2);
    tot += __shfl_xor_sync(0xffffffffu, tot, 1);
    if (lane == 0) g_xsqp[row0 >> 9][warp & 15] = tot;
}

// ---------------------------------------------------------------------------
// Forward recursion (linear domain), pipelined scalar-sum formulation.
// p'_j = w_j*(B^T p)_j + eps*S*w_j;   S' = R + eps*S*Wt,  R = sum_j w_j (B^T p)_j
// Wt precomputed in the GEMM epilogue. Branchless 16-step blocks, ring
// prefetch of depth 16, renorm per block using S captured 2 steps early.
// Lanes 0..31: states 0..31 (p); lanes 0..7 also hold w-padded states 32..39
// (35..39 are zero so their q stays exactly 0).
// ---------------------------------------------------------------------------
struct FwdLane {
    int i1, i2, iF;
    bool is0, lt2, lt8;
};

__device__ __forceinline__ void fwd_step(float& p, float& q, float& S,
                                         float wp, float wq, float Ws,
                                         const FwdLane& L) {
    const unsigned FULL = 0xffffffffu;
    const float EPS = 0.02f / 35.0f;
    float A1 = __shfl_up_sync(FULL, p, 1);     // p[l-1]
    float A2 = __shfl_up_sync(FULL, p, 2);     // p[l-2]
    float Cr = __shfl_sync(FULL, q, L.i1);
    float Dr = __shfl_sync(FULL, q, L.i2);
    float Fv = __shfl_sync(FULL, p, L.iF);
    float Gv = __shfl_sync(FULL, p, 31);
    float pm1 = L.is0 ? Cr : A1;
    float pm2 = L.lt2 ? Dr : A2;
    float qm1 = L.is0 ? Gv : Cr;
    float qm2 = L.lt2 ? Fv : Dr;
    float sp = fmaf(0.1f, p, fmaf(0.8f, pm1, 0.08f * pm2));
    float sq = fmaf(0.1f, q, fmaf(0.8f, qm1, 0.08f * qm2));
    float rp = wp * sp;
    float rq = L.lt8 ? (wq * sq) : 0.0f;
    float sigma = EPS * S;                     // S from previous step
    p = fmaf(sigma, wp, rp);
    q = L.lt8 ? fmaf(sigma, wq, rq) : 0.0f;
    float R = rp + rq;
    R += __shfl_xor_sync(FULL, R, 16);
    R += __shfl_xor_sync(FULL, R, 8);
    R += __shfl_xor_sync(FULL, R, 4);
    R += __shfl_xor_sync(FULL, R, 2);
    R += __shfl_xor_sync(FULL, R, 1);
    S = fmaf(sigma, Ws, R);                    // sum of the NEW p
}

__global__ void __launch_bounds__(32) k_fwd(float* __restrict__ out) {
    const int b = blockIdx.x;
    const int l = threadIdx.x;
    const float* wb = g_w + (size_t)b * TT * NPAD;
    const float* wsb = g_wsum + b * TT;
    const float NEG_INV = -1.0f / 500.0f;
    const unsigned FULL = 0xffffffffu;

    // |x|^2 offset
    float part = (l < 16) ? g_xsqp[b][l] : 0.0f;
    float xoff = part;
    xoff += __shfl_xor_sync(FULL, xoff, 8);
    xoff += __shfl_xor_sync(FULL, xoff, 4);
    xoff += __shfl_xor_sync(FULL, xoff, 2);
    xoff += __shfl_xor_sync(FULL, xoff, 1);
    xoff = __shfl_sync(FULL, xoff, 0) * NEG_INV;

    FwdLane L;
    L.i1 = (l + 2) % 3;
    L.i2 = (l + 1) % 3;
    L.iF = (30 + l) & 31;
    L.is0 = (l == 0);
    L.lt2 = (l < 2);
    L.lt8 = (l < 8);

    // t = 0: alpha0 = emis0 + prior; prior = +10 (s=0), -10 else; shift by 10.
    const float EXPM20 = 2.0611536e-09f;
    float p = wb[l] * (L.is0 ? 1.0f : EXPM20);
    float q = L.lt8 ? (wb[32 + l] * EXPM20) : 0.0f;   // states 35..39 are 0
    float Cacc = 10.0f;
    float S = p + q;
    S += __shfl_xor_sync(FULL, S, 16);
    S += __shfl_xor_sync(FULL, S, 8);
    S += __shfl_xor_sync(FULL, S, 4);
    S += __shfl_xor_sync(FULL, S, 2);
    S += __shfl_xor_sync(FULL, S, 1);

    // ring prefetch, depth 16 (t = 1..16)
    float bufp[16], bufq[16], bufw[16];
    const float* rp0 = wb + NPAD;            // row t=1
#pragma unroll
    for (int d = 0; d < 16; d++) {
        bufp[d] = __ldg(rp0 + d * NPAD + l);
        bufq[d] = L.lt8 ? __ldg(rp0 + d * NPAD + 32 + l) : 0.0f;
        bufw[d] = __ldg(wsb + 1 + d);
    }

    // 31 blocks of 16 steps: t = 1..496; prefetch t+16 (padding makes it safe)
    const float* ldp = wb + 17 * NPAD;       // row t=17
    const float* lds_ = wsb + 17;
    float Ssave = S;
    for (int blk = 0; blk < 31; blk++) {
#pragma unroll
        for (int u = 0; u < 16; u++) {
            fwd_step(p, q, S, bufp[u], bufq[u], bufw[u], L);
            if (u == 13) Ssave = S;
            bufp[u] = __ldg(ldp + u * NPAD + l);
            bufq[u] = L.lt8 ? __ldg(ldp + u * NPAD + 32 + l) : 0.0f;
            bufw[u] = __ldg(lds_ + u);
        }
        float rs = __fdividef(1.0f, Ssave);
        Cacc += __logf(Ssave);
        p *= rs; q *= rs; S *= rs;
        ldp += 16 * NPAD;
        lds_ += 16;
    }
    // tail: 15 steps, t = 497..511
#pragma unroll
    for (int u = 0; u < 15; u++)
        fwd_step(p, q, S, bufp[u], bufq[u], bufw[u], L);

    float v = p + q;
    v += __shfl_xor_sync(FULL, v, 16);
    v += __shfl_xor_sync(FULL, v, 8);
    v += __shfl_xor_sync(FULL, v, 4);
    v += __shfl_xor_sync(FULL, v, 2);
    v += __shfl_xor_sync(FULL, v, 1);
    if (l == 0) out[b] = __logf(v) + Cacc + xoff;
}

// ---------------------------------------------------------------------------
extern "C" void kernel_launch(void* const* d_in, const int* in_sizes, int n_in,
                              void* d_out, int out_size) {
    const float* obs = (const float*)d_in[0];  // [64,512,16,13,12]
    const float* m   = (const float*)d_in[1];  // [35,16,13,12]
    float* out = (float*)d_out;                // [64]

    k_gemm<<<BTROWS / 128, 128>>>(obs, m);     // 256 CTAs x 4 warps x 32 rows
    k_fwd<<<NB, 32>>>(out);
}

// round 6
// speedup vs baseline: 2.3620x; 1.9307x over previous
#include <cuda_runtime.h>
#include <cstdint>

#define NSTATES 35
#define NB      64
#define TT      512
#define DDIM    2496
#define BTROWS  (NB * TT)   // 32768
#define ROWW    80          // [w(40) | kappa(40)] per (b,t) row
#define KC      64          // fp32 elems per k-chunk
#define NCH     39          // 2496/64

// Scratch (no cudaMalloc). +16 pad rows so k_fwd ring prefetch never branches.
__device__ float g_w[(size_t)(BTROWS + 16) * ROWW];
__device__ float g_wsum[BTROWS + 16];
__device__ float g_xsqp[NB][16];

// ---------------------------------------------------------------------------
// helpers
// ---------------------------------------------------------------------------
__device__ __forceinline__ uint32_t smem_u32(const void* p) {
    return (uint32_t)__cvta_generic_to_shared(p);
}
__device__ __forceinline__ uint32_t cvt_bf2(float lo, float hi) {
    uint32_t r;
    asm("cvt.rn.bf16x2.f32 %0, %1, %2;" : "=r"(r) : "f"(hi), "f"(lo));
    return r;
}
__device__ __forceinline__ void mma_bf16(float* d,
    uint32_t a0, uint32_t a1, uint32_t a2, uint32_t a3, uint32_t b0, uint32_t b1) {
    asm volatile(
        "mma.sync.aligned.m16n8k16.row.col.f32.bf16.bf16.f32 "
        "{%0,%1,%2,%3}, {%4,%5,%6,%7}, {%8,%9}, {%0,%1,%2,%3};\n"
        : "+f"(d[0]), "+f"(d[1]), "+f"(d[2]), "+f"(d[3])
        : "r"(a0), "r"(a1), "r"(a2), "r"(a3), "r"(b0), "r"(b1));
}
__device__ __forceinline__ void ldsm4(uint32_t* r, uint32_t a) {
    asm volatile("ldmatrix.sync.aligned.m8n8.x4.shared.b16 {%0,%1,%2,%3}, [%4];"
        : "=r"(r[0]), "=r"(r[1]), "=r"(r[2]), "=r"(r[3]) : "r"(a));
}
__device__ __forceinline__ void ldsm2(uint32_t* r, uint32_t a) {
    asm volatile("ldmatrix.sync.aligned.m8n8.x2.shared.b16 {%0,%1}, [%2];"
        : "=r"(r[0]), "=r"(r[1]) : "r"(a));
}
__device__ __forceinline__ void sts64(uint32_t addr, uint32_t a, uint32_t b) {
    asm volatile("st.shared.v2.b32 [%0], {%1,%2};" :: "r"(addr), "r"(a), "r"(b));
}
__device__ __forceinline__ float bfly_sum(float v) {
    const unsigned FULL = 0xffffffffu;
    v += __shfl_xor_sync(FULL, v, 16);
    v += __shfl_xor_sync(FULL, v, 8);
    v += __shfl_xor_sync(FULL, v, 4);
    v += __shfl_xor_sync(FULL, v, 2);
    v += __shfl_xor_sync(FULL, v, 1);
    return v;
}

// ---------------------------------------------------------------------------
// GEMM: smem-staged bf16 m16n8k16. CTA = 128 thr (4 warps), 128 rows, KC=64.
// A staged coalesced (LDG.128, 2 rows per warp-load), converted to bf16 into
// swizzled smem; fragments via ldmatrix. B (35 rows, zero-padded to 40) staged
// once per chunk and reused by all warps. m_sq / |x|^2 accumulated in exact
// fp32 from the staged values. Epilogue computes w, kappa, row sums.
// ---------------------------------------------------------------------------
__global__ void __launch_bounds__(128) k_gemm(const float* __restrict__ x,
                                              const float* __restrict__ mM) {
    __shared__ __align__(16) unsigned char smraw[21504];  // A 16384 | B 5120
    __shared__ float msq[40];
    const int tid = threadIdx.x, wid = tid >> 5, lane = tid & 31;
    const int wstart = wid * 32;
    const int hhalf = lane >> 4;      // which row of a staged pair
    const int l4 = lane & 15;         // float4 index within 64-float row chunk
    const int xl = lane & 7;
    const int rowBase = blockIdx.x * 128;
    const uint32_t smA = smem_u32(smraw);
    const uint32_t smB = smA + 16384;

    // ldmatrix row-base addresses (swizzle: row&7 == lane&7 since tiles 8-aligned)
    const uint32_t aAddr0 = smA + (uint32_t)(wstart + 0 * 16 + l4) * 128;
    const uint32_t aAddr1 = smA + (uint32_t)(wstart + 1 * 16 + l4) * 128;
    uint32_t bAddr[5];
#pragma unroll
    for (int nt = 0; nt < 5; nt++) bAddr[nt] = smB + (uint32_t)(nt * 8 + xl) * 128;
    const int hvA = hhalf;
    const int hvB = (lane >> 3) & 1;

    float acc[2][5][4];
#pragma unroll
    for (int mt = 0; mt < 2; mt++)
#pragma unroll
        for (int nt = 0; nt < 5; nt++)
#pragma unroll
            for (int i = 0; i < 4; i++) acc[mt][nt][i] = 0.f;

    float xa0 = 0.f, xa1 = 0.f, xa2 = 0.f, xa3 = 0.f;
    float bacc[5] = {0.f, 0.f, 0.f, 0.f, 0.f};

    float4 av[16], bvf[5];

#define LOADCHUNK(CH) do {                                                      \
    int kc0 = (CH) * KC;                                                        \
    _Pragma("unroll")                                                           \
    for (int i = 0; i < 16; i++) {                                              \
        int r = wstart + i * 2 + hhalf;                                         \
        av[i] = *(const float4*)(x + (size_t)(rowBase + r) * DDIM + kc0 + l4*4);\
    }                                                                           \
    _Pragma("unroll")                                                           \
    for (int k = 0; k < 5; k++) {                                               \
        int s = (wid + 4 * k) * 2 + hhalf;                                      \
        int ss = s < NSTATES ? s : NSTATES - 1;                                 \
        float4 t = *(const float4*)(mM + (size_t)ss * DDIM + kc0 + l4 * 4);     \
        if (s >= NSTATES) { t.x = 0.f; t.y = 0.f; t.z = 0.f; t.w = 0.f; }       \
        bvf[k] = t;                                                             \
    } } while (0)

#define CVTSTS() do {                                                           \
    _Pragma("unroll")                                                           \
    for (int i = 0; i < 16; i++) {                                              \
        int sr = wstart + i * 2 + hhalf;                                        \
        float4 v = av[i];                                                       \
        xa0 = fmaf(v.x, v.x, xa0); xa1 = fmaf(v.y, v.y, xa1);                   \
        xa2 = fmaf(v.z, v.z, xa2); xa3 = fmaf(v.w, v.w, xa3);                   \
        uint32_t lo = cvt_bf2(v.x, v.y), hi = cvt_bf2(v.z, v.w);                \
        uint32_t ad = smA + (uint32_t)sr * 128                                  \
                    + (uint32_t)((((l4 >> 1) ^ (sr & 7)) << 4) + ((l4 & 1) << 3)); \
        sts64(ad, lo, hi);                                                      \
    }                                                                           \
    _Pragma("unroll")                                                           \
    for (int k = 0; k < 5; k++) {                                               \
        int s = (wid + 4 * k) * 2 + hhalf;                                      \
        float4 v = bvf[k];                                                      \
        bacc[k] = fmaf(v.x, v.x, fmaf(v.y, v.y, fmaf(v.z, v.z,                  \
                  fmaf(v.w, v.w, bacc[k]))));                                   \
        uint32_t lo = cvt_bf2(v.x, v.y), hi = cvt_bf2(v.z, v.w);                \
        uint32_t ad = smB + (uint32_t)s * 128                                   \
                    + (uint32_t)((((l4 >> 1) ^ (s & 7)) << 4) + ((l4 & 1) << 3)); \
        sts64(ad, lo, hi);                                                      \
    } } while (0)

#define MMASEC() do {                                                           \
    _Pragma("unroll")                                                           \
    for (int kt = 0; kt < 4; kt++) {                                            \
        uint32_t A0[4], A1[4];                                                  \
        uint32_t offA = (uint32_t)(((kt * 2 + hvA) ^ xl) << 4);                 \
        ldsm4(A0, aAddr0 + offA);                                               \
        ldsm4(A1, aAddr1 + offA);                                               \
        uint32_t offB = (uint32_t)(((kt * 2 + hvB) ^ xl) << 4);                 \
        _Pragma("unroll")                                                       \
        for (int nt = 0; nt < 5; nt++) {                                        \
            uint32_t B[2];                                                      \
            ldsm2(B, bAddr[nt] + offB);                                         \
            mma_bf16(acc[0][nt], A0[0], A0[1], A0[2], A0[3], B[0], B[1]);       \
            mma_bf16(acc[1][nt], A1[0], A1[1], A1[2], A1[3], B[0], B[1]);       \
        }                                                                       \
    } } while (0)

    // prologue: stage chunk 0
    LOADCHUNK(0);
    CVTSTS();
    __syncthreads();

    for (int ch = 0; ch < NCH; ch++) {
        bool more = (ch + 1 < NCH);
        if (more) LOADCHUNK(ch + 1);   // LDG latency hidden behind MMA section
        MMASEC();
        __syncthreads();
        if (more) {
            CVTSTS();
            __syncthreads();
        }
    }

    // exact fp32 m_sq: reduce bacc over the 16 lanes sharing each B row
#pragma unroll
    for (int k = 0; k < 5; k++) {
        float v = bacc[k];
        v += __shfl_xor_sync(0xffffffffu, v, 1);
        v += __shfl_xor_sync(0xffffffffu, v, 2);
        v += __shfl_xor_sync(0xffffffffu, v, 4);
        v += __shfl_xor_sync(0xffffffffu, v, 8);
        int s = (wid + 4 * k) * 2 + hhalf;
        if (l4 == 0) msq[s] = v;
    }
    __syncthreads();

    // w = exp((m_sq - 2*xm)/-500) -> smem staging [128][42] (reuses A|B buffer)
    float* wsm = (float*)smraw;
    const int g = lane >> 2, c = lane & 3;
    const float NEG_INV = -1.0f / 500.0f;
#pragma unroll
    for (int mt = 0; mt < 2; mt++) {
#pragma unroll
        for (int h = 0; h < 2; h++) {
            int rl = wstart + mt * 16 + g + h * 8;
#pragma unroll
            for (int nt = 0; nt < 5; nt++) {
                int col = nt * 8 + 2 * c;
                float v0 = acc[mt][nt][2 * h + 0];
                float v1 = acc[mt][nt][2 * h + 1];
                float w0 = (col     < NSTATES) ? __expf((msq[col]     - 2.f * v0) * NEG_INV) : 0.f;
                float w1 = (col + 1 < NSTATES) ? __expf((msq[col + 1] - 2.f * v1) * NEG_INV) : 0.f;
                *(float2*)&wsm[rl * 42 + col] = make_float2(w0, w1);
            }
        }
    }
    __syncthreads();

    // per-thread row pass: Wt, kappa, write [w|kappa] to g_w
    {
        int rl = tid;
        float wv[40];
#pragma unroll
        for (int j = 0; j < 40; j++) wv[j] = wsm[rl * 42 + j];
        float Wt = 0.f;
#pragma unroll
        for (int j = 0; j < NSTATES; j++) Wt += wv[j];
        float kap[40];
#pragma unroll
        for (int j = 0; j < NSTATES; j++) {
            int j1 = (j + 1) % NSTATES, j2 = (j + 2) % NSTATES;
            kap[j] = fmaf(0.1f, wv[j], fmaf(0.8f, wv[j1], 0.08f * wv[j2]));
        }
#pragma unroll
        for (int j = NSTATES; j < 40; j++) kap[j] = 0.f;
        float* gr = g_w + (size_t)(rowBase + rl) * ROWW;
#pragma unroll
        for (int j = 0; j < 40; j += 4)
            *(float4*)(gr + j) = make_float4(wv[j], wv[j+1], wv[j+2], wv[j+3]);
#pragma unroll
        for (int j = 0; j < 40; j += 4)
            *(float4*)(gr + 40 + j) = make_float4(kap[j], kap[j+1], kap[j+2], kap[j+3]);
        g_wsum[rowBase + rl] = Wt;
    }

    // |x|^2 partial per warp (32 rows, all within batch b = row0>>9)
    float tot = bfly_sum(xa0 + xa1 + xa2 + xa3);
    if (lane == 0)
        g_xsqp[(rowBase + wstart) >> 9][(blockIdx.x * 4 + wid) & 15] = tot;
}

// ---------------------------------------------------------------------------
// Forward recursion. kappa-form: R_t = sum_i p_{t-1,i} * kappa_{t,i} starts
// its butterfly from p directly -> 2-step slack on the S chain (Δ >= ~71cyc).
// p'_j = w_j*(Λp)_j + eps*S*w_j ;  S' = R + eps*S*Wt. out = log(S) + Cacc + xoff.
// ---------------------------------------------------------------------------
struct FwdLane { int i1, i2, iF; bool is0, lt2; };

__device__ __forceinline__ void fwd_step2(float& p, float& q, float& S, float& Rn,
                                          float wp, float wq, float Ws,
                                          float kpn, float kqn, const FwdLane& L) {
    const unsigned FULL = 0xffffffffu;
    const float EPS = 0.02f / 35.0f;
    float sigma = EPS * S;                     // S_{t-1}: ready
    float A1 = __shfl_up_sync(FULL, p, 1);
    float A2 = __shfl_up_sync(FULL, p, 2);
    float Cr = __shfl_sync(FULL, q, L.i1);
    float Dr = __shfl_sync(FULL, q, L.i2);
    float Fv = __shfl_sync(FULL, p, L.iF);
    float Gv = __shfl_sync(FULL, p, 31);
    float pm1 = L.is0 ? Cr : A1;
    float pm2 = L.lt2 ? Dr : A2;
    float qm1 = L.is0 ? Gv : Cr;
    float qm2 = L.lt2 ? Fv : Dr;
    float sp = fmaf(0.1f, p, fmaf(0.8f, pm1, 0.08f * pm2));
    float sq = fmaf(0.1f, q, fmaf(0.8f, qm1, 0.08f * qm2));
    float rp = wp * sp;
    float rq = wq * sq;                        // wq==0 on pad lanes -> q stays 0
    p = fmaf(sigma, wp, rp);
    q = fmaf(sigma, wq, rq);
    S = fmaf(sigma, Ws, Rn);                   // S_t (Rn = R_t, bfly from last step)
    float z = fmaf(q, kqn, p * kpn);           // start R_{t+1} bfly from new p
    z += __shfl_xor_sync(FULL, z, 16);
    z += __shfl_xor_sync(FULL, z, 8);
    z += __shfl_xor_sync(FULL, z, 4);
    z += __shfl_xor_sync(FULL, z, 2);
    z += __shfl_xor_sync(FULL, z, 1);
    Rn = z;
}

__global__ void __launch_bounds__(32) k_fwd(float* __restrict__ out) {
    const int b = blockIdx.x;
    const int l = threadIdx.x;
    const float* wb = g_w + (size_t)b * TT * ROWW;
    const float* wsb = g_wsum + b * TT;
    const float NEG_INV = -1.0f / 500.0f;
    const bool lt8 = (l < 8);

    float part = (l < 16) ? g_xsqp[b][l] : 0.0f;
    float xoff = bfly_sum(part) * NEG_INV;

    FwdLane L;
    L.i1 = (l + 2) % 3;
    L.i2 = (l + 1) % 3;
    L.iF = (30 + l) & 31;
    L.is0 = (l == 0);
    L.lt2 = (l < 2);

    // t = 0 init (prior shift +10)
    const float EXPM20 = 2.0611536e-09f;
    float p = wb[l] * (L.is0 ? 1.0f : EXPM20);
    float q = lt8 ? (wb[32 + l] * EXPM20) : 0.0f;   // pad states' w are 0
    float Cacc = 10.0f;
    float S = bfly_sum(p + q);

    // ring prefetch depth 16 (t = 1..16)
    float bufp[16], bufq[16], bufkp[16], bufkq[16], bufw[16];
#pragma unroll
    for (int d = 0; d < 16; d++) {
        const float* rp = wb + (size_t)(1 + d) * ROWW;
        bufp[d]  = __ldg(rp + l);
        bufq[d]  = lt8 ? __ldg(rp + 32 + l) : 0.0f;
        bufkp[d] = __ldg(rp + 40 + l);
        bufkq[d] = lt8 ? __ldg(rp + 72 + l) : 0.0f;
        bufw[d]  = __ldg(wsb + 1 + d);
    }
    // R_1 = sum p_0 * kappa_1
    float Rn = bfly_sum(fmaf(q, bufkq[0], p * bufkp[0]));

    const float* ldp = wb + (size_t)17 * ROWW;
    const float* ldsw = wsb + 17;
    float rsave = 1.0f, lsave = 0.0f;
    for (int blk = 0; blk < 31; blk++) {       // t = 1..496
#pragma unroll
        for (int u = 0; u < 16; u++) {
            fwd_step2(p, q, S, Rn, bufp[u], bufq[u], bufw[u],
                      bufkp[(u + 1) & 15], bufkq[(u + 1) & 15], L);
            bufp[u]  = __ldg(ldp + u * ROWW + l);
            bufq[u]  = lt8 ? __ldg(ldp + u * ROWW + 32 + l) : 0.0f;
            bufkp[u] = __ldg(ldp + u * ROWW + 40 + l);
            bufkq[u] = lt8 ? __ldg(ldp + u * ROWW + 72 + l) : 0.0f;
            bufw[u]  = __ldg(ldsw + u);
            if (u == 13) { rsave = __fdividef(1.0f, S); lsave = __logf(S); }
        }
        // renorm with a 2-step-old scale (any positive scale is exact)
        p *= rsave; q *= rsave; S *= rsave; Rn *= rsave; Cacc += lsave;
        ldp += 16 * ROWW;
        ldsw += 16;
    }
    // tail: t = 497..511
#pragma unroll
    for (int u = 0; u < 15; u++)
        fwd_step2(p, q, S, Rn, bufp[u], bufq[u], bufw[u],
                  bufkp[(u + 1) & 15], bufkq[(u + 1) & 15], L);

    if (l == 0) out[b] = __logf(S) + Cacc + xoff;
}

// ---------------------------------------------------------------------------
extern "C" void kernel_launch(void* const* d_in, const int* in_sizes, int n_in,
                              void* d_out, int out_size) {
    const float* obs = (const float*)d_in[0];  // [64,512,16,13,12]
    const float* m   = (const float*)d_in[1];  // [35,16,13,12]
    float* out = (float*)d_out;                // [64]

    k_gemm<<<BTROWS / 128, 128>>>(obs, m);     // 256 CTAs x 4 warps x 32 rows
    k_fwd<<<NB, 32>>>(out);
}